// round 1
// baseline (speedup 1.0000x reference)
#include <cuda_runtime.h>
#include <cuda_bf16.h>
#include <math.h>

#define Hh 128
#define Rr 50
#define Ll 4
#define Nn 10000
#define Mm 64
#define NP 10048           // 157 * 64, padded rows for guard-free GEMM tiles
#define EMAX 2000000
#define EPB 64

// ---------------- scratch (static device globals; no allocation) ----------------
__device__ float g_x[NP * Hh];
__device__ float g_y[NP * Hh];
__device__ float g_S[NP * Hh];
__device__ float g_aggr[NP * Hh];
__device__ float g_gi[NP * 3 * Hh];
__device__ float g_deg[NP];
__device__ float g_d[EMAX];
__device__ float g_sums[Mm * Hh];
__device__ float g_cnt[Mm];

// ---------------- utility kernels ----------------
__global__ void zero_k(float* p, int n) {
    int i = blockIdx.x * blockDim.x + threadIdx.x;
    if (i < n) p[i] = 0.f;
}

__global__ void init_x(const int* __restrict__ an, const float* __restrict__ emb,
                       float* __restrict__ x) {
    int i = blockIdx.x * blockDim.x + threadIdx.x;
    if (i >= Nn * Hh) return;
    int n = i >> 7, ch = i & 127;
    int a = an[n];
    a = a < 0 ? 0 : (a > 99 ? 99 : a);
    x[i] = emb[a * Hh + ch];
}

__global__ void edge_dist(const float* __restrict__ pos, const int* __restrict__ rowp,
                          const int* __restrict__ colp, int E,
                          float* __restrict__ dv, float* __restrict__ deg) {
    int e = blockIdx.x * blockDim.x + threadIdx.x;
    if (e >= E) return;
    int r = rowp[e], c = colp[e];
    float dx = pos[r * 3 + 0] - pos[c * 3 + 0];
    float dy = pos[r * 3 + 1] - pos[c * 3 + 1];
    float dz = pos[r * 3 + 2] - pos[c * 3 + 2];
    dv[e] = sqrtf(dx * dx + dy * dy + dz * dz);
    atomicAdd(&deg[c], 1.0f);
}

// ---------------- fp32 tiled GEMM: C[M,N] = A[M,K=128] @ B[128,N] + bias + deg*bias2 ----------------
__global__ void __launch_bounds__(256)
gemm128(const float* __restrict__ A, const float* __restrict__ B,
        const float* __restrict__ bias, const float* __restrict__ deg,
        const float* __restrict__ bias2, float* __restrict__ C, int Nr) {
    const int K = 128;
    __shared__ float As[16][64];
    __shared__ float Bs[16][64];
    int tx = threadIdx.x & 15, ty = threadIdx.x >> 4;
    int m0 = blockIdx.y * 64, n0 = blockIdx.x * 64;
    float acc[4][4] = {};
    for (int kk = 0; kk < K; kk += 16) {
        {
            int t = threadIdx.x;
            int r = t >> 2;
            int c4 = (t & 3) << 2;
            float4 v = *reinterpret_cast<const float4*>(A + (m0 + r) * K + kk + c4);
            As[c4 + 0][r] = v.x; As[c4 + 1][r] = v.y;
            As[c4 + 2][r] = v.z; As[c4 + 3][r] = v.w;
        }
        {
            int t = threadIdx.x;
            int r = t >> 4;
            int c4 = (t & 15) << 2;
            float4 v = *reinterpret_cast<const float4*>(B + (kk + r) * Nr + n0 + c4);
            *reinterpret_cast<float4*>(&Bs[r][c4]) = v;
        }
        __syncthreads();
#pragma unroll
        for (int k = 0; k < 16; k++) {
            float a[4], b[4];
#pragma unroll
            for (int i = 0; i < 4; i++) a[i] = As[k][ty * 4 + i];
#pragma unroll
            for (int j = 0; j < 4; j++) b[j] = Bs[k][tx * 4 + j];
#pragma unroll
            for (int i = 0; i < 4; i++)
#pragma unroll
                for (int j = 0; j < 4; j++) acc[i][j] += a[i] * b[j];
        }
        __syncthreads();
    }
#pragma unroll
    for (int i = 0; i < 4; i++) {
        int m = m0 + ty * 4 + i;
        float dm = deg ? deg[m] : 0.f;
#pragma unroll
        for (int j = 0; j < 4; j++) {
            int n = n0 + tx * 4 + j;
            float v = acc[i][j];
            if (bias) v += bias[n];
            if (bias2) v += dm * bias2[n];
            C[m * Nr + n] = v;
        }
    }
}

// ---------------- edge MLP: S[row] += silu(y[col] + rbf(d) @ W1b) ----------------
// Exploits exact graph symmetry (edges sorted by row) for register accumulation.
__global__ void __launch_bounds__(128)
edge_mlp(const int* __restrict__ rowp, const int* __restrict__ colp, int E,
         const float* __restrict__ dvec, const float* __restrict__ y,
         const float* __restrict__ W1b, float* __restrict__ S) {
    __shared__ float rbf[52];
    int tid = threadIdx.x;
    float w[Rr];
#pragma unroll
    for (int k = 0; k < Rr; k++) w[k] = W1b[k * Hh + tid];

    int e0 = blockIdx.x * EPB;
    int e1 = min(e0 + EPB, E);
    float acc = 0.f;
    int cur = -1;
    for (int e = e0; e < e1; e++) {
        if (tid < Rr) {
            float t = dvec[e] - (float)tid * (5.0f / 49.0f);
            rbf[tid] = expf(-50.0f * t * t);  // 1/(2*width^2), width=0.1
        }
        __syncthreads();
        int rr = rowp[e], cc = colp[e];
        float pre = y[cc * Hh + tid];
#pragma unroll
        for (int k4 = 0; k4 < 48; k4 += 4) {
            float4 rv = *reinterpret_cast<const float4*>(&rbf[k4]);
            pre += rv.x * w[k4];
            pre += rv.y * w[k4 + 1];
            pre += rv.z * w[k4 + 2];
            pre += rv.w * w[k4 + 3];
        }
        pre += rbf[48] * w[48] + rbf[49] * w[49];
        float sv = pre / (1.f + expf(-pre));  // silu
        if (rr != cur) {
            if (cur >= 0) atomicAdd(&S[cur * Hh + tid], acc);
            cur = rr;
            acc = 0.f;
        }
        acc += sv;
        __syncthreads();  // protect rbf before next overwrite
    }
    if (cur >= 0) atomicAdd(&S[cur * Hh + tid], acc);
}

// ---------------- GRU update (h0 = 0) ----------------
__global__ void gru_update(const float* __restrict__ gi, const float* __restrict__ bhh,
                           float* __restrict__ x) {
    int i = blockIdx.x * blockDim.x + threadIdx.x;
    if (i >= Nn * Hh) return;
    int n = i >> 7, ch = i & 127;
    const float* g = gi + n * 3 * Hh;
    float r = 1.f / (1.f + expf(-(g[ch] + bhh[ch])));
    float z = 1.f / (1.f + expf(-(g[Hh + ch] + bhh[Hh + ch])));
    float nv = tanhf(g[2 * Hh + ch] + r * bhh[2 * Hh + ch]);
    x[i] += (1.f - z) * nv;
}

// ---------------- LayerNorm + pooling scatter ----------------
__global__ void ln_pool(const float* __restrict__ x, const int* __restrict__ batch,
                        const float* __restrict__ lg, const float* __restrict__ lb,
                        float* __restrict__ out, float* __restrict__ sums,
                        float* __restrict__ cnt) {
    int warp = (blockIdx.x * blockDim.x + threadIdx.x) >> 5;
    int lane = threadIdx.x & 31;
    if (warp >= Nn) return;
    const float4* xr = reinterpret_cast<const float4*>(x + warp * Hh);
    float4 v = xr[lane];
    float s = v.x + v.y + v.z + v.w;
#pragma unroll
    for (int o = 16; o; o >>= 1) s += __shfl_xor_sync(~0u, s, o);
    float mu = s * (1.0f / 128.0f);
    float dx = v.x - mu, dy = v.y - mu, dz = v.z - mu, dw = v.w - mu;
    float vs = dx * dx + dy * dy + dz * dz + dw * dw;
#pragma unroll
    for (int o = 16; o; o >>= 1) vs += __shfl_xor_sync(~0u, vs, o);
    float inv = rsqrtf(vs * (1.0f / 128.0f) + 1e-5f);
    int ch = lane * 4;
    float o0 = dx * inv * lg[ch + 0] + lb[ch + 0];
    float o1 = dy * inv * lg[ch + 1] + lb[ch + 1];
    float o2 = dz * inv * lg[ch + 2] + lb[ch + 2];
    float o3 = dw * inv * lg[ch + 3] + lb[ch + 3];
    float4 ov = make_float4(o0, o1, o2, o3);
    *reinterpret_cast<float4*>(out + warp * Hh + ch) = ov;
    int bm = batch[warp];
    atomicAdd(&sums[bm * Hh + ch + 0], o0);
    atomicAdd(&sums[bm * Hh + ch + 1], o1);
    atomicAdd(&sums[bm * Hh + ch + 2], o2);
    atomicAdd(&sums[bm * Hh + ch + 3], o3);
    if (lane == 0) atomicAdd(&cnt[bm], 1.0f);
}

__global__ void pool_final(const float* __restrict__ sums, const float* __restrict__ cnt,
                           float* __restrict__ out2) {
    int i = blockIdx.x * blockDim.x + threadIdx.x;
    if (i >= Mm * Hh) return;
    int m = i >> 7;
    float c = cnt[m];
    out2[i] = sums[i] / (c < 1.f ? 1.f : c);
}

// ---------------- host launcher ----------------
extern "C" void kernel_launch(void* const* d_in, const int* in_sizes, int n_in,
                              void* d_out, int out_size) {
    const int*   an    = (const int*)d_in[0];
    const float* pos   = (const float*)d_in[1];
    const int*   batch = (const int*)d_in[2];
    const int*   eidx  = (const int*)d_in[3];
    const float* emb   = (const float*)d_in[4];
    const float* W1    = (const float*)d_in[5];
    const float* b1    = (const float*)d_in[6];
    const float* W2    = (const float*)d_in[7];
    const float* b2    = (const float*)d_in[8];
    const float* W_ih  = (const float*)d_in[9];
    const float* b_ih  = (const float*)d_in[10];
    const float* b_hh  = (const float*)d_in[11];
    const float* ln_g  = (const float*)d_in[12];
    const float* ln_b  = (const float*)d_in[13];
    int E = in_sizes[3] / 2;
    if (E > EMAX) E = EMAX;
    const int* rowp = eidx;
    const int* colp = eidx + E;
    float* out = (float*)d_out;

    float *xp, *yp, *Sp, *ap, *gp, *dp, *dvp, *sp, *cp;
    cudaGetSymbolAddress((void**)&xp,  g_x);
    cudaGetSymbolAddress((void**)&yp,  g_y);
    cudaGetSymbolAddress((void**)&Sp,  g_S);
    cudaGetSymbolAddress((void**)&ap,  g_aggr);
    cudaGetSymbolAddress((void**)&gp,  g_gi);
    cudaGetSymbolAddress((void**)&dp,  g_deg);
    cudaGetSymbolAddress((void**)&dvp, g_d);
    cudaGetSymbolAddress((void**)&sp,  g_sums);
    cudaGetSymbolAddress((void**)&cp,  g_cnt);

    // init
    init_x<<<(Nn * Hh + 255) / 256, 256>>>(an, emb, xp);
    zero_k<<<(NP + 255) / 256, 256>>>(dp, NP);
    zero_k<<<(Mm * Hh + 255) / 256, 256>>>(sp, Mm * Hh);
    zero_k<<<(Mm + 255) / 256, 256>>>(cp, Mm);
    edge_dist<<<(E + 255) / 256, 256>>>(pos, rowp, colp, E, dvp, dp);

    dim3 g_y128((Hh + 63) / 64, NP / 64);   // 2 x 157
    dim3 g_y384((3 * Hh + 63) / 64, NP / 64);  // 6 x 157

    for (int l = 0; l < Ll; l++) {
        const float* W1a = W1 + l * (Hh + Rr) * Hh;            // rows [0,128)
        const float* W1b = W1 + l * (Hh + Rr) * Hh + Hh * Hh;  // rows [128,178)
        // y = x @ W1a + b1[l]
        gemm128<<<g_y128, 256>>>(xp, W1a, b1 + l * Hh, nullptr, nullptr, yp, Hh);
        // zero S, then edge MLP with register-resident accumulation
        zero_k<<<(NP * Hh + 255) / 256, 256>>>(Sp, NP * Hh);
        edge_mlp<<<(E + EPB - 1) / EPB, 128>>>(rowp, colp, E, dvp, yp, W1b, Sp);
        // aggr = S @ W2[l] + deg (x) b2[l]
        gemm128<<<g_y128, 256>>>(Sp, W2 + l * Hh * Hh, nullptr, dp, b2 + l * Hh, ap, Hh);
        // gi = aggr @ W_ih[l] + b_ih[l]
        gemm128<<<g_y384, 256>>>(ap, W_ih + l * Hh * 3 * Hh, b_ih + l * 3 * Hh,
                                 nullptr, nullptr, gp, 3 * Hh);
        // GRU update
        gru_update<<<(Nn * Hh + 255) / 256, 256>>>(gp, b_hh + l * 3 * Hh, xp);
    }

    // LayerNorm + pooling
    float* out_x = out;
    float* out_rep = out + Nn * Hh;
    if (out_size == Mm * Hh) {  // defensive: harness wants only graph_rep
        out_x = yp;             // scratch
        out_rep = out;
    }
    ln_pool<<<(Nn * 32 + 255) / 256, 256>>>(xp, batch, ln_g, ln_b, out_x, sp, cp);
    pool_final<<<(Mm * Hh + 127) / 128, 128>>>(sp, cp, out_rep);
}

// round 2
// speedup vs baseline: 1.7638x; 1.7638x over previous
#include <cuda_runtime.h>
#include <cuda_bf16.h>
#include <math.h>

#define Hh 128
#define Rr 50
#define Ll 4
#define Nn 10000
#define Mm 64
#define NP 10112           // 79 * 128, padded rows for guard-free 128-row GEMM tiles
#define EMAX 2000000
#define EPB2 128
#define BINS 2048
#define SCALE ((float)BINS / 5.0f)
#define STEP (5.0f / (float)BINS)

typedef unsigned long long u64;

__device__ __forceinline__ void fma2(u64 &d, u64 a, u64 b) {
    asm("fma.rn.f32x2 %0, %1, %2, %0;" : "+l"(d) : "l"(a), "l"(b));
}
__device__ __forceinline__ u64 pack2(float lo, float hi) {
    u64 r; asm("mov.b64 %0, {%1, %2};" : "=l"(r) : "f"(lo), "f"(hi)); return r;
}
__device__ __forceinline__ void unpack2(u64 v, float &lo, float &hi) {
    asm("mov.b64 {%0, %1}, %2;" : "=f"(lo), "=f"(hi) : "l"(v));
}

// ---------------- scratch (static device globals; no allocation) ----------------
__device__ float  g_x[NP * Hh];
__device__ float  g_y[NP * Hh];
__device__ float  g_S[NP * Hh];
__device__ float  g_gi[NP * 3 * Hh];
__device__ float  g_deg[NP];
__device__ float  g_d[EMAX];
__device__ float  g_sums[Mm * Hh];
__device__ float  g_cnt[Mm];
__device__ float2 g_tab[Ll * BINS * Hh];
__device__ float  g_Wc[Ll * Hh * 3 * Hh];
__device__ float  g_bc2[Ll * 3 * Hh];

// ---------------- utility kernels ----------------
__global__ void zero_k(float* p, int n) {
    int i = blockIdx.x * blockDim.x + threadIdx.x;
    if (i < n) p[i] = 0.f;
}

__global__ void init_x(const int* __restrict__ an, const float* __restrict__ emb,
                       float* __restrict__ x) {
    int i = blockIdx.x * blockDim.x + threadIdx.x;
    if (i >= Nn * Hh) return;
    int n = i >> 7, ch = i & 127;
    int a = an[n];
    a = a < 0 ? 0 : (a > 99 ? 99 : a);
    x[i] = emb[a * Hh + ch];
}

__global__ void edge_dist(const float* __restrict__ pos, const int* __restrict__ rowp,
                          const int* __restrict__ colp, int E,
                          float* __restrict__ dv, float* __restrict__ deg) {
    int e = blockIdx.x * blockDim.x + threadIdx.x;
    if (e >= E) return;
    int r = rowp[e], c = colp[e];
    float dx = pos[r * 3 + 0] - pos[c * 3 + 0];
    float dy = pos[r * 3 + 1] - pos[c * 3 + 1];
    float dz = pos[r * 3 + 2] - pos[c * 3 + 2];
    dv[e] = sqrtf(dx * dx + dy * dy + dz * dz);
    atomicAdd(&deg[c], 1.0f);
}

// ---------------- rbf lerp-table build: tab[l][b][ch] = (V(b), V(b+1)-V(b)) ----------------
__global__ void build_tab(const float* __restrict__ W1, float2* __restrict__ tab) {
    int b = blockIdx.x, l = blockIdx.y, tid = threadIdx.x;
    __shared__ float r0[Rr], r1[Rr];
    if (tid < Rr) {
        float c = (float)tid * (5.0f / 49.0f);
        float t0 = (float)b * STEP - c;
        float t1 = (float)(b + 1) * STEP - c;
        r0[tid] = expf(-50.0f * t0 * t0);
        r1[tid] = expf(-50.0f * t1 * t1);
    }
    __syncthreads();
    const float* W1b = W1 + l * (Hh + Rr) * Hh + Hh * Hh;
    float v0 = 0.f, v1 = 0.f;
#pragma unroll
    for (int k = 0; k < Rr; k++) {
        float w = W1b[k * Hh + tid];
        v0 += r0[k] * w;
        v1 += r1[k] * w;
    }
    tab[((l * BINS + b) << 7) + tid] = make_float2(v0, v1 - v0);
}

// ---------------- bc2[l] = b2[l] @ W_ih[l] ----------------
__global__ void make_bc2(const float* __restrict__ W_ih, const float* __restrict__ b2,
                         float* __restrict__ bc2) {
    int l = blockIdx.y;
    int n = blockIdx.x * 128 + threadIdx.x;
    const float* W = W_ih + l * Hh * 3 * Hh;
    const float* b = b2 + l * Hh;
    float s = 0.f;
#pragma unroll 8
    for (int k = 0; k < Hh; k++) s += b[k] * W[k * 3 * Hh + n];
    bc2[l * 3 * Hh + n] = s;
}

// ---------------- f32x2 GEMM: C[M,Nr] = A[M,128] @ B[128,Nr] + bias + deg*bias2 --------------
// tile 128x64, 256 threads, 8Mx4N per thread, M-paired f32x2 accumulators.
__global__ void __launch_bounds__(256)
gemm_f2(const float* __restrict__ A, const float* __restrict__ B,
        const float* __restrict__ bias, const float* __restrict__ deg,
        const float* __restrict__ bias2, float* __restrict__ C, int Nr) {
    __shared__ float As[16][132];
    __shared__ float Bs[16][64];
    int tid = threadIdx.x;
    int tx = tid & 15, ty = tid >> 4;
    int m0 = blockIdx.y * 128, n0 = blockIdx.x * 64;
    u64 acc[4][4] = {};
    for (int kk = 0; kk < 128; kk += 16) {
#pragma unroll
        for (int it = 0; it < 2; it++) {
            int r = (tid >> 2) + it * 64;
            int c4 = (tid & 3) << 2;
            float4 v = *(const float4*)(A + (size_t)(m0 + r) * 128 + kk + c4);
            As[c4 + 0][r] = v.x; As[c4 + 1][r] = v.y;
            As[c4 + 2][r] = v.z; As[c4 + 3][r] = v.w;
        }
        {
            int r = tid >> 4, c4 = (tid & 15) << 2;
            *(float4*)&Bs[r][c4] = *(const float4*)(B + (size_t)(kk + r) * Nr + n0 + c4);
        }
        __syncthreads();
#pragma unroll
        for (int k = 0; k < 16; k++) {
            longlong2 la = *(const longlong2*)&As[k][ty * 8];
            longlong2 lb = *(const longlong2*)&As[k][ty * 8 + 4];
            float4 bv = *(const float4*)&Bs[k][tx * 4];
            u64 ap[4] = { (u64)la.x, (u64)la.y, (u64)lb.x, (u64)lb.y };
            u64 bp[4] = { pack2(bv.x, bv.x), pack2(bv.y, bv.y),
                          pack2(bv.z, bv.z), pack2(bv.w, bv.w) };
#pragma unroll
            for (int i = 0; i < 4; i++)
#pragma unroll
                for (int j = 0; j < 4; j++) fma2(acc[i][j], ap[i], bp[j]);
        }
        __syncthreads();
    }
    float4 bb = make_float4(0.f, 0.f, 0.f, 0.f);
    float4 b2v = make_float4(0.f, 0.f, 0.f, 0.f);
    if (bias)  bb  = *(const float4*)(bias + n0 + tx * 4);
    if (bias2) b2v = *(const float4*)(bias2 + n0 + tx * 4);
#pragma unroll
    for (int i = 0; i < 4; i++) {
        int mA = m0 + ty * 8 + 2 * i;
        float dA = deg ? deg[mA] : 0.f;
        float dB = deg ? deg[mA + 1] : 0.f;
        float lo0, hi0, lo1, hi1, lo2, hi2, lo3, hi3;
        unpack2(acc[i][0], lo0, hi0);
        unpack2(acc[i][1], lo1, hi1);
        unpack2(acc[i][2], lo2, hi2);
        unpack2(acc[i][3], lo3, hi3);
        float4 rA = make_float4(lo0 + bb.x + dA * b2v.x, lo1 + bb.y + dA * b2v.y,
                                lo2 + bb.z + dA * b2v.z, lo3 + bb.w + dA * b2v.w);
        float4 rB = make_float4(hi0 + bb.x + dB * b2v.x, hi1 + bb.y + dB * b2v.y,
                                hi2 + bb.z + dB * b2v.z, hi3 + bb.w + dB * b2v.w);
        *(float4*)(C + (size_t)mA * Nr + n0 + tx * 4) = rA;
        *(float4*)(C + (size_t)(mA + 1) * Nr + n0 + tx * 4) = rB;
    }
}

// ---------------- edge MLP via table: S[row] += silu(y[col] + lerp(tab, d)) ----------------
// No barriers; register accumulation over sorted row runs; 1-deep prefetch pipeline.
__global__ void __launch_bounds__(128)
edge_mlp2(const int* __restrict__ rowp, const int* __restrict__ colp, int E,
          const float* __restrict__ dvec, const float* __restrict__ y,
          const float2* __restrict__ tab, float* __restrict__ S) {
    int tid = threadIdx.x;
    int e0 = blockIdx.x * EPB2;
    int e1 = min(e0 + EPB2, E);
    if (e0 >= e1) return;
    float acc = 0.f;
    int cur = -1;
    float dN = __ldg(dvec + e0);
    int rrN = __ldg(rowp + e0);
    int ccN = __ldg(colp + e0);
    for (int e = e0; e < e1; e++) {
        float d = dN; int rr = rrN, cc = ccN;
        if (e + 1 < e1) {
            dN = __ldg(dvec + e + 1);
            rrN = __ldg(rowp + e + 1);
            ccN = __ldg(colp + e + 1);
        }
        float u = d * SCALE;
        int b = (int)u;
        float f = u - (float)b;
        float2 ts = __ldg(&tab[(b << 7) + tid]);
        float pre = __ldg(&y[((size_t)cc << 7) + tid]) + ts.x + f * ts.y;
        float sv = pre / (1.f + __expf(-pre));
        if (rr != cur) {
            if (cur >= 0) atomicAdd(&S[((size_t)cur << 7) + tid], acc);
            cur = rr;
            acc = 0.f;
        }
        acc += sv;
    }
    if (cur >= 0) atomicAdd(&S[((size_t)cur << 7) + tid], acc);
}

// ---------------- GRU update (h0 = 0) ----------------
__global__ void gru_update(const float* __restrict__ gi, const float* __restrict__ bhh,
                           float* __restrict__ x) {
    int i = blockIdx.x * blockDim.x + threadIdx.x;
    if (i >= Nn * Hh) return;
    int n = i >> 7, ch = i & 127;
    const float* g = gi + (size_t)n * 3 * Hh;
    float r = 1.f / (1.f + expf(-(g[ch] + bhh[ch])));
    float z = 1.f / (1.f + expf(-(g[Hh + ch] + bhh[Hh + ch])));
    float nv = tanhf(g[2 * Hh + ch] + r * bhh[2 * Hh + ch]);
    x[i] += (1.f - z) * nv;
}

// ---------------- LayerNorm + pooling scatter ----------------
__global__ void ln_pool(const float* __restrict__ x, const int* __restrict__ batch,
                        const float* __restrict__ lg, const float* __restrict__ lb,
                        float* __restrict__ out, float* __restrict__ sums,
                        float* __restrict__ cnt) {
    int warp = (blockIdx.x * blockDim.x + threadIdx.x) >> 5;
    int lane = threadIdx.x & 31;
    if (warp >= Nn) return;
    const float4* xr = reinterpret_cast<const float4*>(x + (size_t)warp * Hh);
    float4 v = xr[lane];
    float s = v.x + v.y + v.z + v.w;
#pragma unroll
    for (int o = 16; o; o >>= 1) s += __shfl_xor_sync(~0u, s, o);
    float mu = s * (1.0f / 128.0f);
    float dx = v.x - mu, dy = v.y - mu, dz = v.z - mu, dw = v.w - mu;
    float vs = dx * dx + dy * dy + dz * dz + dw * dw;
#pragma unroll
    for (int o = 16; o; o >>= 1) vs += __shfl_xor_sync(~0u, vs, o);
    float inv = rsqrtf(vs * (1.0f / 128.0f) + 1e-5f);
    int ch = lane * 4;
    float o0 = dx * inv * lg[ch + 0] + lb[ch + 0];
    float o1 = dy * inv * lg[ch + 1] + lb[ch + 1];
    float o2 = dz * inv * lg[ch + 2] + lb[ch + 2];
    float o3 = dw * inv * lg[ch + 3] + lb[ch + 3];
    *reinterpret_cast<float4*>(out + (size_t)warp * Hh + ch) = make_float4(o0, o1, o2, o3);
    int bm = batch[warp];
    atomicAdd(&sums[bm * Hh + ch + 0], o0);
    atomicAdd(&sums[bm * Hh + ch + 1], o1);
    atomicAdd(&sums[bm * Hh + ch + 2], o2);
    atomicAdd(&sums[bm * Hh + ch + 3], o3);
    if (lane == 0) atomicAdd(&cnt[bm], 1.0f);
}

__global__ void pool_final(const float* __restrict__ sums, const float* __restrict__ cnt,
                           float* __restrict__ out2) {
    int i = blockIdx.x * blockDim.x + threadIdx.x;
    if (i >= Mm * Hh) return;
    int m = i >> 7;
    float c = cnt[m];
    out2[i] = sums[i] / (c < 1.f ? 1.f : c);
}

// ---------------- host launcher ----------------
extern "C" void kernel_launch(void* const* d_in, const int* in_sizes, int n_in,
                              void* d_out, int out_size) {
    const int*   an    = (const int*)d_in[0];
    const float* pos   = (const float*)d_in[1];
    const int*   batch = (const int*)d_in[2];
    const int*   eidx  = (const int*)d_in[3];
    const float* emb   = (const float*)d_in[4];
    const float* W1    = (const float*)d_in[5];
    const float* b1    = (const float*)d_in[6];
    const float* W2    = (const float*)d_in[7];
    const float* b2    = (const float*)d_in[8];
    const float* W_ih  = (const float*)d_in[9];
    const float* b_ih  = (const float*)d_in[10];
    const float* b_hh  = (const float*)d_in[11];
    const float* ln_g  = (const float*)d_in[12];
    const float* ln_b  = (const float*)d_in[13];
    int E = in_sizes[3] / 2;
    if (E > EMAX) E = EMAX;
    const int* rowp = eidx;
    const int* colp = eidx + E;
    float* out = (float*)d_out;

    float *xp, *yp, *Sp, *gp, *dp, *dvp, *sp, *cp, *wcp, *bcp;
    float2* tp;
    cudaGetSymbolAddress((void**)&xp,  g_x);
    cudaGetSymbolAddress((void**)&yp,  g_y);
    cudaGetSymbolAddress((void**)&Sp,  g_S);
    cudaGetSymbolAddress((void**)&gp,  g_gi);
    cudaGetSymbolAddress((void**)&dp,  g_deg);
    cudaGetSymbolAddress((void**)&dvp, g_d);
    cudaGetSymbolAddress((void**)&sp,  g_sums);
    cudaGetSymbolAddress((void**)&cp,  g_cnt);
    cudaGetSymbolAddress((void**)&tp,  g_tab);
    cudaGetSymbolAddress((void**)&wcp, g_Wc);
    cudaGetSymbolAddress((void**)&bcp, g_bc2);

    // init + precompute
    init_x<<<(Nn * Hh + 255) / 256, 256>>>(an, emb, xp);
    zero_k<<<(NP + 255) / 256, 256>>>(dp, NP);
    zero_k<<<(Mm * Hh + 255) / 256, 256>>>(sp, Mm * Hh);
    zero_k<<<(Mm + 255) / 256, 256>>>(cp, Mm);
    edge_dist<<<(E + 255) / 256, 256>>>(pos, rowp, colp, E, dvp, dp);
    build_tab<<<dim3(BINS, Ll), 128>>>(W1, tp);
    make_bc2<<<dim3(3, Ll), 128>>>(W_ih, b2, bcp);
    for (int l = 0; l < Ll; l++) {
        // Wc[l] = W2[l] @ W_ih[l]   (128 x 384)
        gemm_f2<<<dim3(6, 1), 256>>>(W2 + l * Hh * Hh, W_ih + l * Hh * 3 * Hh,
                                     nullptr, nullptr, nullptr,
                                     wcp + l * Hh * 3 * Hh, 3 * Hh);
    }

    dim3 g_y128(2, NP / 128);
    dim3 g_y384(6, NP / 128);

    for (int l = 0; l < Ll; l++) {
        const float* W1a = W1 + l * (Hh + Rr) * Hh;
        // y = x @ W1a + b1[l]
        gemm_f2<<<g_y128, 256>>>(xp, W1a, b1 + l * Hh, nullptr, nullptr, yp, Hh);
        // zero S, then table-based edge MLP
        zero_k<<<(NP * Hh + 255) / 256, 256>>>(Sp, NP * Hh);
        edge_mlp2<<<(E + EPB2 - 1) / EPB2, 128>>>(rowp, colp, E, dvp, yp,
                                                  tp + l * BINS * Hh, Sp);
        // gi = S @ Wc[l] + b_ih[l] + deg (x) bc2[l]
        gemm_f2<<<g_y384, 256>>>(Sp, wcp + l * Hh * 3 * Hh, b_ih + l * 3 * Hh,
                                 dp, bcp + l * 3 * Hh, gp, 3 * Hh);
        // GRU update
        gru_update<<<(Nn * Hh + 255) / 256, 256>>>(gp, b_hh + l * 3 * Hh, xp);
    }

    // LayerNorm + pooling
    float* out_x = out;
    float* out_rep = out + Nn * Hh;
    if (out_size == Mm * Hh) {
        out_x = yp;
        out_rep = out;
    }
    ln_pool<<<(Nn * 32 + 255) / 256, 256>>>(xp, batch, ln_g, ln_b, out_x, sp, cp);
    pool_final<<<(Mm * Hh + 127) / 128, 128>>>(sp, cp, out_rep);
}

// round 3
// speedup vs baseline: 2.4959x; 1.4150x over previous
#include <cuda_runtime.h>
#include <cuda_bf16.h>
#include <math.h>

#define Hh 128
#define Rr 50
#define Ll 4
#define Nn 10000
#define Mm 64
#define NP 10112           // 79 * 128
#define EMAX 2000000
#define BINS 2048
#define SCALE ((float)BINS / 5.0f)
#define STEP (5.0f / (float)BINS)

typedef unsigned long long u64;

__device__ __forceinline__ void fma2(u64 &d, u64 a, u64 b) {
    asm("fma.rn.f32x2 %0, %1, %2, %0;" : "+l"(d) : "l"(a), "l"(b));
}
__device__ __forceinline__ u64 pack2(float lo, float hi) {
    u64 r; asm("mov.b64 %0, {%1, %2};" : "=l"(r) : "f"(lo), "f"(hi)); return r;
}
__device__ __forceinline__ void unpack2(u64 v, float &lo, float &hi) {
    asm("mov.b64 {%0, %1}, %2;" : "=f"(lo), "=f"(hi) : "l"(v));
}

__device__ __forceinline__ float gru_upd(float xo, float rv, float zv, float nv,
                                         float bhr, float bhz, float bhn) {
    float r = __fdividef(1.f, 1.f + __expf(-(rv + bhr)));
    float z = __fdividef(1.f, 1.f + __expf(-(zv + bhz)));
    float t = nv + r * bhn;
    float e = __expf(2.f * t);
    float th = 1.f - __fdividef(2.f, e + 1.f);
    return xo + (1.f - z) * th;
}

// ---------------- scratch ----------------
__device__ float  g_x[NP * Hh];
__device__ float  g_y[NP * Hh];
__device__ float  g_S[NP * Hh];
__device__ float  g_gi[NP * 3 * Hh];
__device__ float  g_d[EMAX];
__device__ int    g_rp[Nn + 1];
__device__ float  g_sums[Mm * Hh];
__device__ float  g_cnt[Mm];
__device__ float2 g_tab[Ll * BINS * Hh];
__device__ float  g_Wc[Ll * Hh * 3 * Hh];
__device__ float  g_bc2[Ll * 3 * Hh];
__device__ int    g_ctr;

// ---------------- prep0: init x (+pads), zero sums/cnt, build row_ptr ----------------
__global__ void prep0(const int* __restrict__ an, const float* __restrict__ emb,
                      const int* __restrict__ rowp, int E,
                      float* __restrict__ x, float* __restrict__ sums,
                      float* __restrict__ cnt, int* __restrict__ rp) {
    int i = blockIdx.x * blockDim.x + threadIdx.x;
    if (i < NP * Hh) {
        int n = i >> 7, ch = i & 127;
        if (n < Nn) {
            int a = an[n];
            a = a < 0 ? 0 : (a > 99 ? 99 : a);
            x[i] = emb[a * Hh + ch];
        } else {
            x[i] = 0.f;
        }
        return;
    }
    int i2 = i - NP * Hh;
    if (i2 < Mm * Hh) { sums[i2] = 0.f; return; }
    i2 -= Mm * Hh;
    if (i2 < Mm) { cnt[i2] = 0.f; return; }
    int e = i2 - Mm;
    if (e > E) return;
    if (e == 0) {
        int b = rowp[0];
        for (int r = 0; r <= b; r++) rp[r] = 0;
    } else if (e == E) {
        int a = rowp[E - 1];
        for (int r = a + 1; r <= Nn; r++) rp[r] = E;
    } else {
        int a = rowp[e - 1], b = rowp[e];
        for (int r = a + 1; r <= b; r++) rp[r] = e;
    }
}

// ---------------- prep1: edge distances + rbf table + bc2 ----------------
__global__ void prep1(const float* __restrict__ pos, const int* __restrict__ rowp,
                      const int* __restrict__ colp, int E, int ndb,
                      const float* __restrict__ W1, const float* __restrict__ W_ih,
                      const float* __restrict__ b2,
                      float* __restrict__ dv, float2* __restrict__ tab,
                      float* __restrict__ bc2) {
    __shared__ float r0[Rr], r1[Rr];
    int tid = threadIdx.x;
    int blk = blockIdx.x;
    if (blk < ndb) {
        int e = blk * 128 + tid;
        if (e < E) {
            int r = rowp[e], c = colp[e];
            float dx = pos[r * 3 + 0] - pos[c * 3 + 0];
            float dy = pos[r * 3 + 1] - pos[c * 3 + 1];
            float dz = pos[r * 3 + 2] - pos[c * 3 + 2];
            dv[e] = sqrtf(dx * dx + dy * dy + dz * dz);
        }
        return;
    }
    int t = blk - ndb;
    if (t < BINS * Ll) {
        int l = t / BINS, b = t - l * BINS;
        if (tid < Rr) {
            float c = (float)tid * (5.0f / 49.0f);
            float t0 = (float)b * STEP - c;
            float t1 = (float)(b + 1) * STEP - c;
            r0[tid] = expf(-50.0f * t0 * t0);
            r1[tid] = expf(-50.0f * t1 * t1);
        }
        __syncthreads();
        const float* W1b = W1 + l * (Hh + Rr) * Hh + Hh * Hh;
        float v0 = 0.f, v1 = 0.f;
#pragma unroll
        for (int k = 0; k < Rr; k++) {
            float w = W1b[k * Hh + tid];
            v0 += r0[k] * w;
            v1 += r1[k] * w;
        }
        tab[((l * BINS + b) << 7) + tid] = make_float2(v0, v1 - v0);
        return;
    }
    int t2 = t - BINS * Ll;           // [0, 12): bc2 = b2 @ W_ih
    int l = t2 / 3, chunk = t2 - l * 3;
    int n = chunk * 128 + tid;
    const float* W = W_ih + l * Hh * 3 * Hh;
    const float* b = b2 + l * Hh;
    float s = 0.f;
#pragma unroll 8
    for (int k = 0; k < Hh; k++) s += b[k] * W[k * 3 * Hh + n];
    bc2[l * 3 * Hh + n] = s;
}

// ---------------- f32x2 GEMM, tile 128x128, optional fused GRU prologue ----------------
// C[.,Nr] = A'[.,128] @ B[128,Nr] + bias + deg*bias2, where
// A' = A when gi==null, else A' = A + gru_upd(gi,bhh) (and A' stored to xout).
__global__ void __launch_bounds__(256, 2)
gemm_f2b(const float* __restrict__ A, const float* __restrict__ B,
         const float* __restrict__ bias, const int* __restrict__ rp,
         const float* __restrict__ bias2,
         const float* __restrict__ gi, const float* __restrict__ bhh,
         float* __restrict__ xout,
         float* __restrict__ C, int Nr,
         int aSz, int bSz, int cSz) {
    __shared__ float As[16][132];
    __shared__ float Bs[16][128];
    int tid = threadIdx.x;
    int tx = tid & 15, ty = tid >> 4;
    int m0 = blockIdx.y * 128, n0 = blockIdx.x * 128;
    const float* Ab = A + (size_t)blockIdx.z * aSz;
    const float* Bb = B + (size_t)blockIdx.z * bSz;
    float* Cb = C + (size_t)blockIdx.z * cSz;
    u64 acc[4][8] = {};
    for (int kk = 0; kk < 128; kk += 16) {
#pragma unroll
        for (int it = 0; it < 2; it++) {
            int r = (tid >> 2) + it * 64;
            int c4 = (tid & 3) << 2;
            int m = m0 + r;
            float4 v = *(const float4*)(Ab + (size_t)m * 128 + kk + c4);
            if (gi) {
                const float* gm = gi + (size_t)m * 384 + kk + c4;
                float4 rv = __ldg((const float4*)(gm));
                float4 zv = __ldg((const float4*)(gm + 128));
                float4 nv = __ldg((const float4*)(gm + 256));
                float4 br = __ldg((const float4*)(bhh + kk + c4));
                float4 bz = __ldg((const float4*)(bhh + 128 + kk + c4));
                float4 bn = __ldg((const float4*)(bhh + 256 + kk + c4));
                v.x = gru_upd(v.x, rv.x, zv.x, nv.x, br.x, bz.x, bn.x);
                v.y = gru_upd(v.y, rv.y, zv.y, nv.y, br.y, bz.y, bn.y);
                v.z = gru_upd(v.z, rv.z, zv.z, nv.z, br.z, bz.z, bn.z);
                v.w = gru_upd(v.w, rv.w, zv.w, nv.w, br.w, bz.w, bn.w);
                *(float4*)(xout + (size_t)m * 128 + kk + c4) = v;
            }
            As[c4 + 0][r] = v.x; As[c4 + 1][r] = v.y;
            As[c4 + 2][r] = v.z; As[c4 + 3][r] = v.w;
        }
        {
            int r = tid >> 4, c8 = (tid & 15) << 3;
            *(float4*)&Bs[r][c8]     = *(const float4*)(Bb + (size_t)(kk + r) * Nr + n0 + c8);
            *(float4*)&Bs[r][c8 + 4] = *(const float4*)(Bb + (size_t)(kk + r) * Nr + n0 + c8 + 4);
        }
        __syncthreads();
#pragma unroll
        for (int k = 0; k < 16; k++) {
            longlong2 la = *(const longlong2*)&As[k][ty * 8];
            longlong2 lb = *(const longlong2*)&As[k][ty * 8 + 4];
            float4 b0 = *(const float4*)&Bs[k][tx * 8];
            float4 b1 = *(const float4*)&Bs[k][tx * 8 + 4];
            u64 ap[4] = { (u64)la.x, (u64)la.y, (u64)lb.x, (u64)lb.y };
            u64 bp[8] = { pack2(b0.x, b0.x), pack2(b0.y, b0.y),
                          pack2(b0.z, b0.z), pack2(b0.w, b0.w),
                          pack2(b1.x, b1.x), pack2(b1.y, b1.y),
                          pack2(b1.z, b1.z), pack2(b1.w, b1.w) };
#pragma unroll
            for (int i = 0; i < 4; i++)
#pragma unroll
                for (int j = 0; j < 8; j++) fma2(acc[i][j], ap[i], bp[j]);
        }
        __syncthreads();
    }
    float4 bb0 = make_float4(0.f, 0.f, 0.f, 0.f), bb1 = bb0;
    float4 c20 = bb0, c21 = bb0;
    if (bias)  { bb0 = *(const float4*)(bias + n0 + tx * 8);
                 bb1 = *(const float4*)(bias + n0 + tx * 8 + 4); }
    if (bias2) { c20 = *(const float4*)(bias2 + n0 + tx * 8);
                 c21 = *(const float4*)(bias2 + n0 + tx * 8 + 4); }
#pragma unroll
    for (int i = 0; i < 4; i++) {
        int mA = m0 + ty * 8 + 2 * i;
        float dA = 0.f, dB = 0.f;
        if (rp) {
            if (mA < Nn)     dA = (float)(rp[mA + 1] - rp[mA]);
            if (mA + 1 < Nn) dB = (float)(rp[mA + 2] - rp[mA + 1]);
        }
        float lo[8], hi[8];
#pragma unroll
        for (int j = 0; j < 8; j++) unpack2(acc[i][j], lo[j], hi[j]);
        float4 rA0 = make_float4(lo[0] + bb0.x + dA * c20.x, lo[1] + bb0.y + dA * c20.y,
                                 lo[2] + bb0.z + dA * c20.z, lo[3] + bb0.w + dA * c20.w);
        float4 rA1 = make_float4(lo[4] + bb1.x + dA * c21.x, lo[5] + bb1.y + dA * c21.y,
                                 lo[6] + bb1.z + dA * c21.z, lo[7] + bb1.w + dA * c21.w);
        float4 rB0 = make_float4(hi[0] + bb0.x + dB * c20.x, hi[1] + bb0.y + dB * c20.y,
                                 hi[2] + bb0.z + dB * c20.z, hi[3] + bb0.w + dB * c20.w);
        float4 rB1 = make_float4(hi[4] + bb1.x + dB * c21.x, hi[5] + bb1.y + dB * c21.y,
                                 hi[6] + bb1.z + dB * c21.z, hi[7] + bb1.w + dB * c21.w);
        *(float4*)(Cb + (size_t)mA * Nr + n0 + tx * 8)           = rA0;
        *(float4*)(Cb + (size_t)mA * Nr + n0 + tx * 8 + 4)       = rA1;
        *(float4*)(Cb + (size_t)(mA + 1) * Nr + n0 + tx * 8)     = rB0;
        *(float4*)(Cb + (size_t)(mA + 1) * Nr + n0 + tx * 8 + 4) = rB1;
    }
}

// ---------------- CSR edge kernel: S[n] = sum_e silu(y[col_e] + lerp(tab,d_e)) ----------------
__global__ void __launch_bounds__(128)
edge_csr(const int* __restrict__ rp, const int* __restrict__ colp,
         const float* __restrict__ dvec, const float* __restrict__ y,
         const float2* __restrict__ tab, float* __restrict__ S) {
    __shared__ int   s_cc[64];
    __shared__ float s_u[64];
    int n = blockIdx.x;
    int tid = threadIdx.x;
    int e0 = rp[n];
    int deg = rp[n + 1] - e0;
    float acc = 0.f;
    for (int base = 0; base < deg; base += 64) {
        int cnt = min(64, deg - base);
        if (tid < cnt) {
            s_cc[tid] = colp[e0 + base + tid];
            s_u[tid] = dvec[e0 + base + tid] * SCALE;
        }
        __syncthreads();
#pragma unroll 4
        for (int j = 0; j < cnt; j++) {
            float u = s_u[j];
            int cc = s_cc[j];
            int b = (int)u;
            float f = u - (float)b;
            float2 ts = __ldg(&tab[(b << 7) + tid]);
            float pre = __ldg(&y[((size_t)cc << 7) + tid]) + ts.x + f * ts.y;
            acc += __fdividef(pre, 1.f + __expf(-pre));
        }
        __syncthreads();
    }
    S[((size_t)n << 7) + tid] = acc;
}

// ---------------- fused GRU(l=3) + LayerNorm + pooling (+final via last block) ----------------
__global__ void __launch_bounds__(256)
ln_pool_all(const float* __restrict__ x, const float* __restrict__ gi,
            const float* __restrict__ bhh, const int* __restrict__ batch,
            const float* __restrict__ lg, const float* __restrict__ lb,
            float* __restrict__ out, float* __restrict__ sums,
            float* __restrict__ cnt, float* __restrict__ out2) {
    __shared__ int s_last;
    int warp = (blockIdx.x * blockDim.x + threadIdx.x) >> 5;
    int lane = threadIdx.x & 31;
    if (warp < Nn) {
        int ch = lane * 4;
        float4 v = __ldg((const float4*)(x + (size_t)warp * Hh + ch));
        const float* gm = gi + (size_t)warp * 384 + ch;
        float4 rv = __ldg((const float4*)(gm));
        float4 zv = __ldg((const float4*)(gm + 128));
        float4 nv = __ldg((const float4*)(gm + 256));
        float4 br = __ldg((const float4*)(bhh + ch));
        float4 bz = __ldg((const float4*)(bhh + 128 + ch));
        float4 bn = __ldg((const float4*)(bhh + 256 + ch));
        v.x = gru_upd(v.x, rv.x, zv.x, nv.x, br.x, bz.x, bn.x);
        v.y = gru_upd(v.y, rv.y, zv.y, nv.y, br.y, bz.y, bn.y);
        v.z = gru_upd(v.z, rv.z, zv.z, nv.z, br.z, bz.z, bn.z);
        v.w = gru_upd(v.w, rv.w, zv.w, nv.w, br.w, bz.w, bn.w);
        float s = v.x + v.y + v.z + v.w;
#pragma unroll
        for (int o = 16; o; o >>= 1) s += __shfl_xor_sync(~0u, s, o);
        float mu = s * (1.0f / 128.0f);
        float dx = v.x - mu, dy = v.y - mu, dz = v.z - mu, dw = v.w - mu;
        float vs = dx * dx + dy * dy + dz * dz + dw * dw;
#pragma unroll
        for (int o = 16; o; o >>= 1) vs += __shfl_xor_sync(~0u, vs, o);
        float inv = rsqrtf(vs * (1.0f / 128.0f) + 1e-5f);
        float o0 = dx * inv * lg[ch + 0] + lb[ch + 0];
        float o1 = dy * inv * lg[ch + 1] + lb[ch + 1];
        float o2 = dz * inv * lg[ch + 2] + lb[ch + 2];
        float o3 = dw * inv * lg[ch + 3] + lb[ch + 3];
        *(float4*)(out + (size_t)warp * Hh + ch) = make_float4(o0, o1, o2, o3);
        int bm = batch[warp];
        atomicAdd(&sums[bm * Hh + ch + 0], o0);
        atomicAdd(&sums[bm * Hh + ch + 1], o1);
        atomicAdd(&sums[bm * Hh + ch + 2], o2);
        atomicAdd(&sums[bm * Hh + ch + 3], o3);
        if (lane == 0) atomicAdd(&cnt[bm], 1.0f);
    }
    __syncthreads();
    if (threadIdx.x == 0) {
        __threadfence();
        int t = atomicAdd(&g_ctr, 1);
        s_last = (t == gridDim.x - 1) ? 1 : 0;
    }
    __syncthreads();
    if (s_last) {
        for (int i = threadIdx.x; i < Mm * Hh; i += blockDim.x) {
            float c = cnt[i >> 7];
            out2[i] = sums[i] / (c < 1.f ? 1.f : c);
        }
        if (threadIdx.x == 0) g_ctr = 0;
    }
}

// ---------------- host launcher ----------------
extern "C" void kernel_launch(void* const* d_in, const int* in_sizes, int n_in,
                              void* d_out, int out_size) {
    const int*   an    = (const int*)d_in[0];
    const float* pos   = (const float*)d_in[1];
    const int*   batch = (const int*)d_in[2];
    const int*   eidx  = (const int*)d_in[3];
    const float* emb   = (const float*)d_in[4];
    const float* W1    = (const float*)d_in[5];
    const float* b1    = (const float*)d_in[6];
    const float* W2    = (const float*)d_in[7];
    const float* b2    = (const float*)d_in[8];
    const float* W_ih  = (const float*)d_in[9];
    const float* b_ih  = (const float*)d_in[10];
    const float* b_hh  = (const float*)d_in[11];
    const float* ln_g  = (const float*)d_in[12];
    const float* ln_b  = (const float*)d_in[13];
    int E = in_sizes[3] / 2;
    if (E > EMAX) E = EMAX;
    const int* rowp = eidx;
    const int* colp = eidx + E;
    float* out = (float*)d_out;

    float *xp, *yp, *Sp, *gp, *dvp, *sp, *cp, *wcp, *bcp;
    float2* tp;
    int* rpp;
    cudaGetSymbolAddress((void**)&xp,  g_x);
    cudaGetSymbolAddress((void**)&yp,  g_y);
    cudaGetSymbolAddress((void**)&Sp,  g_S);
    cudaGetSymbolAddress((void**)&gp,  g_gi);
    cudaGetSymbolAddress((void**)&dvp, g_d);
    cudaGetSymbolAddress((void**)&rpp, g_rp);
    cudaGetSymbolAddress((void**)&sp,  g_sums);
    cudaGetSymbolAddress((void**)&cp,  g_cnt);
    cudaGetSymbolAddress((void**)&tp,  g_tab);
    cudaGetSymbolAddress((void**)&wcp, g_Wc);
    cudaGetSymbolAddress((void**)&bcp, g_bc2);

    // 1: init x/pads + zero sums/cnt + row_ptr
    int p0n = NP * Hh + Mm * Hh + Mm + E + 1;
    prep0<<<(p0n + 255) / 256, 256>>>(an, emb, rowp, E, xp, sp, cp, rpp);
    // 2: distances + rbf table + bc2
    int ndb = (E + 127) / 128;
    prep1<<<ndb + BINS * Ll + 12, 128>>>(pos, rowp, colp, E, ndb, W1, W_ih, b2,
                                         dvp, tp, bcp);
    const int Mt = NP / 128;
    for (int l = 0; l < Ll; l++) {
        const float* W1a = W1 + l * (Hh + Rr) * Hh;
        // y = x' @ W1a + b1   (x' = x + gru(gi_{l-1}) for l>0, stored back to x)
        gemm_f2b<<<dim3(1, Mt), 256>>>(xp, W1a, b1 + l * Hh, nullptr, nullptr,
                                       (l > 0) ? gp : nullptr,
                                       b_hh + (l - 1) * 3 * Hh, xp,
                                       yp, Hh, 0, 0, 0);
        // edge aggregation (CSR, no atomics)
        edge_csr<<<Nn, 128>>>(rpp, colp, dvp, yp, tp + l * BINS * Hh, Sp);
        if (l == 0) {
            // Wc[l] = W2[l] @ W_ih[l], batched over layers
            gemm_f2b<<<dim3(3, 1, Ll), 256>>>(W2, W_ih, nullptr, nullptr, nullptr,
                                              nullptr, nullptr, nullptr,
                                              wcp, 3 * Hh,
                                              Hh * Hh, Hh * 3 * Hh, Hh * 3 * Hh);
        }
        // gi = S @ Wc + b_ih + deg (x) bc2
        gemm_f2b<<<dim3(3, Mt), 256>>>(Sp, wcp + l * Hh * 3 * Hh, b_ih + l * 3 * Hh,
                                       rpp, bcp + l * 3 * Hh,
                                       nullptr, nullptr, nullptr,
                                       gp, 3 * Hh, 0, 0, 0);
    }

    float* out_x = out;
    float* out_rep = out + Nn * Hh;
    if (out_size == Mm * Hh) { out_x = yp; out_rep = out; }
    // fused GRU(l=3) + LayerNorm + pool + finalize
    ln_pool_all<<<(Nn + 7) / 8, 256>>>(xp, gp, b_hh + 3 * 3 * Hh, batch,
                                       ln_g, ln_b, out_x, sp, cp, out_rep);
}

// round 5
// speedup vs baseline: 2.5924x; 1.0387x over previous
#include <cuda_runtime.h>
#include <cuda_bf16.h>
#include <math.h>

#define Hh 128
#define Rr 50
#define Ll 4
#define Nn 10000
#define Mm 64
#define NP 10112           // 79 * 128
#define EMAX 2000000
#define BINS 2048
#define SCALE ((float)BINS / 5.0f)
#define STEP (5.0f / (float)BINS)

typedef unsigned long long u64;

__device__ __forceinline__ void fma2(u64 &d, u64 a, u64 b) {
    asm("fma.rn.f32x2 %0, %1, %2, %0;" : "+l"(d) : "l"(a), "l"(b));
}
__device__ __forceinline__ u64 pack2(float lo, float hi) {
    u64 r; asm("mov.b64 %0, {%1, %2};" : "=l"(r) : "f"(lo), "f"(hi)); return r;
}
__device__ __forceinline__ void unpack2(u64 v, float &lo, float &hi) {
    asm("mov.b64 {%0, %1}, %2;" : "=f"(lo), "=f"(hi) : "l"(v));
}

__device__ __forceinline__ float gru_upd(float xo, float rv, float zv, float nv,
                                         float bhr, float bhz, float bhn) {
    float r = __fdividef(1.f, 1.f + __expf(-(rv + bhr)));
    float z = __fdividef(1.f, 1.f + __expf(-(zv + bhz)));
    float t = nv + r * bhn;
    float e = __expf(2.f * t);
    float th = 1.f - __fdividef(2.f, e + 1.f);
    return xo + (1.f - z) * th;
}

__device__ __forceinline__ float silu_f(float p) {
    float e = __expf(-p);
    float r;
    asm("rcp.approx.f32 %0, %1;" : "=f"(r) : "f"(1.f + e));
    return p * r;
}

// ---------------- scratch ----------------
__device__ float  g_x[NP * Hh];
__device__ float  g_y[NP * Hh];
__device__ float  g_S[NP * Hh];
__device__ float  g_gi[NP * 3 * Hh];
__device__ float  g_d[EMAX];
__device__ int    g_rp[Nn + 1];
__device__ float  g_sums[Mm * Hh];
__device__ float  g_cnt[Mm];
__device__ float2 g_tab[Ll * BINS * Hh];
__device__ float  g_Wc[Ll * Hh * 3 * Hh];
__device__ float  g_bc2[Ll * 3 * Hh];
__device__ int    g_ctr;

// ---------------- prep0: init x (+pads), zero sums/cnt, build row_ptr ----------------
__global__ void prep0(const int* __restrict__ an, const float* __restrict__ emb,
                      const int* __restrict__ rowp, int E,
                      float* __restrict__ x, float* __restrict__ sums,
                      float* __restrict__ cnt, int* __restrict__ rp) {
    int i = blockIdx.x * blockDim.x + threadIdx.x;
    if (i < NP * Hh) {
        int n = i >> 7, ch = i & 127;
        if (n < Nn) {
            int a = an[n];
            a = a < 0 ? 0 : (a > 99 ? 99 : a);
            x[i] = emb[a * Hh + ch];
        } else {
            x[i] = 0.f;
        }
        return;
    }
    int i2 = i - NP * Hh;
    if (i2 < Mm * Hh) { sums[i2] = 0.f; return; }
    i2 -= Mm * Hh;
    if (i2 < Mm) { cnt[i2] = 0.f; return; }
    int e = i2 - Mm;
    if (e > E) return;
    if (e == 0) {
        int b = rowp[0];
        for (int r = 0; r <= b; r++) rp[r] = 0;
    } else if (e == E) {
        int a = rowp[E - 1];
        for (int r = a + 1; r <= Nn; r++) rp[r] = E;
    } else {
        int a = rowp[e - 1], b = rowp[e];
        for (int r = a + 1; r <= b; r++) rp[r] = e;
    }
}

// ---------------- prep1: edge distances + rbf table + bc2 ----------------
__global__ void prep1(const float* __restrict__ pos, const int* __restrict__ rowp,
                      const int* __restrict__ colp, int E, int ndb,
                      const float* __restrict__ W1, const float* __restrict__ W_ih,
                      const float* __restrict__ b2,
                      float* __restrict__ dv, float2* __restrict__ tab,
                      float* __restrict__ bc2) {
    __shared__ float r0[Rr], r1[Rr];
    int tid = threadIdx.x;
    int blk = blockIdx.x;
    if (blk < ndb) {
        int e = blk * 128 + tid;
        if (e < E) {
            int r = rowp[e], c = colp[e];
            float dx = pos[r * 3 + 0] - pos[c * 3 + 0];
            float dy = pos[r * 3 + 1] - pos[c * 3 + 1];
            float dz = pos[r * 3 + 2] - pos[c * 3 + 2];
            dv[e] = sqrtf(dx * dx + dy * dy + dz * dz);
        }
        return;
    }
    int t = blk - ndb;
    if (t < BINS * Ll) {
        int l = t / BINS, b = t - l * BINS;
        if (tid < Rr) {
            float c = (float)tid * (5.0f / 49.0f);
            float t0 = (float)b * STEP - c;
            float t1 = (float)(b + 1) * STEP - c;
            r0[tid] = expf(-50.0f * t0 * t0);
            r1[tid] = expf(-50.0f * t1 * t1);
        }
        __syncthreads();
        const float* W1b = W1 + l * (Hh + Rr) * Hh + Hh * Hh;
        float v0 = 0.f, v1 = 0.f;
#pragma unroll
        for (int k = 0; k < Rr; k++) {
            float w = W1b[k * Hh + tid];
            v0 += r0[k] * w;
            v1 += r1[k] * w;
        }
        tab[((l * BINS + b) << 7) + tid] = make_float2(v0, v1 - v0);
        return;
    }
    int t2 = t - BINS * Ll;           // [0, 12): bc2 = b2 @ W_ih
    int l = t2 / 3, chunk = t2 - l * 3;
    int n = chunk * 128 + tid;
    const float* W = W_ih + l * Hh * 3 * Hh;
    const float* b = b2 + l * Hh;
    float s = 0.f;
#pragma unroll 8
    for (int k = 0; k < Hh; k++) s += b[k] * W[k * 3 * Hh + n];
    bc2[l * 3 * Hh + n] = s;
}

// ---------------- f32x2 GEMM, tile 128x128, optional fused GRU prologue ----------------
__global__ void __launch_bounds__(256, 2)
gemm_f2b(const float* __restrict__ A, const float* __restrict__ B,
         const float* __restrict__ bias, const int* __restrict__ rp,
         const float* __restrict__ bias2,
         const float* __restrict__ gi, const float* __restrict__ bhh,
         float* __restrict__ xout,
         float* __restrict__ C, int Nr,
         int aSz, int bSz, int cSz) {
    __shared__ float As[16][132];
    __shared__ float Bs[16][128];
    int tid = threadIdx.x;
    int tx = tid & 15, ty = tid >> 4;
    int m0 = blockIdx.y * 128, n0 = blockIdx.x * 128;
    const float* Ab = A + (size_t)blockIdx.z * aSz;
    const float* Bb = B + (size_t)blockIdx.z * bSz;
    float* Cb = C + (size_t)blockIdx.z * cSz;
    u64 acc[4][8] = {};
    for (int kk = 0; kk < 128; kk += 16) {
#pragma unroll
        for (int it = 0; it < 2; it++) {
            int r = (tid >> 2) + it * 64;
            int c4 = (tid & 3) << 2;
            int m = m0 + r;
            float4 v = *(const float4*)(Ab + (size_t)m * 128 + kk + c4);
            if (gi) {
                const float* gm = gi + (size_t)m * 384 + kk + c4;
                float4 rv = __ldg((const float4*)(gm));
                float4 zv = __ldg((const float4*)(gm + 128));
                float4 nv = __ldg((const float4*)(gm + 256));
                float4 br = __ldg((const float4*)(bhh + kk + c4));
                float4 bz = __ldg((const float4*)(bhh + 128 + kk + c4));
                float4 bn = __ldg((const float4*)(bhh + 256 + kk + c4));
                v.x = gru_upd(v.x, rv.x, zv.x, nv.x, br.x, bz.x, bn.x);
                v.y = gru_upd(v.y, rv.y, zv.y, nv.y, br.y, bz.y, bn.y);
                v.z = gru_upd(v.z, rv.z, zv.z, nv.z, br.z, bz.z, bn.z);
                v.w = gru_upd(v.w, rv.w, zv.w, nv.w, br.w, bz.w, bn.w);
                *(float4*)(xout + (size_t)m * 128 + kk + c4) = v;
            }
            As[c4 + 0][r] = v.x; As[c4 + 1][r] = v.y;
            As[c4 + 2][r] = v.z; As[c4 + 3][r] = v.w;
        }
        {
            int r = tid >> 4, c8 = (tid & 15) << 3;
            *(float4*)&Bs[r][c8]     = *(const float4*)(Bb + (size_t)(kk + r) * Nr + n0 + c8);
            *(float4*)&Bs[r][c8 + 4] = *(const float4*)(Bb + (size_t)(kk + r) * Nr + n0 + c8 + 4);
        }
        __syncthreads();
#pragma unroll
        for (int k = 0; k < 16; k++) {
            longlong2 la = *(const longlong2*)&As[k][ty * 8];
            longlong2 lb = *(const longlong2*)&As[k][ty * 8 + 4];
            float4 b0 = *(const float4*)&Bs[k][tx * 8];
            float4 b1 = *(const float4*)&Bs[k][tx * 8 + 4];
            u64 ap[4] = { (u64)la.x, (u64)la.y, (u64)lb.x, (u64)lb.y };
            u64 bp[8] = { pack2(b0.x, b0.x), pack2(b0.y, b0.y),
                          pack2(b0.z, b0.z), pack2(b0.w, b0.w),
                          pack2(b1.x, b1.x), pack2(b1.y, b1.y),
                          pack2(b1.z, b1.z), pack2(b1.w, b1.w) };
#pragma unroll
            for (int i = 0; i < 4; i++)
#pragma unroll
                for (int j = 0; j < 8; j++) fma2(acc[i][j], ap[i], bp[j]);
        }
        __syncthreads();
    }
    float4 bb0 = make_float4(0.f, 0.f, 0.f, 0.f), bb1 = bb0;
    float4 c20 = bb0, c21 = bb0;
    if (bias)  { bb0 = *(const float4*)(bias + n0 + tx * 8);
                 bb1 = *(const float4*)(bias + n0 + tx * 8 + 4); }
    if (bias2) { c20 = *(const float4*)(bias2 + n0 + tx * 8);
                 c21 = *(const float4*)(bias2 + n0 + tx * 8 + 4); }
#pragma unroll
    for (int i = 0; i < 4; i++) {
        int mA = m0 + ty * 8 + 2 * i;
        float dA = 0.f, dB = 0.f;
        if (rp) {
            if (mA < Nn)     dA = (float)(rp[mA + 1] - rp[mA]);
            if (mA + 1 < Nn) dB = (float)(rp[mA + 2] - rp[mA + 1]);
        }
        float lo[8], hi[8];
#pragma unroll
        for (int j = 0; j < 8; j++) unpack2(acc[i][j], lo[j], hi[j]);
        float4 rA0 = make_float4(lo[0] + bb0.x + dA * c20.x, lo[1] + bb0.y + dA * c20.y,
                                 lo[2] + bb0.z + dA * c20.z, lo[3] + bb0.w + dA * c20.w);
        float4 rA1 = make_float4(lo[4] + bb1.x + dA * c21.x, lo[5] + bb1.y + dA * c21.y,
                                 lo[6] + bb1.z + dA * c21.z, lo[7] + bb1.w + dA * c21.w);
        float4 rB0 = make_float4(hi[0] + bb0.x + dB * c20.x, hi[1] + bb0.y + dB * c20.y,
                                 hi[2] + bb0.z + dB * c20.z, hi[3] + bb0.w + dB * c20.w);
        float4 rB1 = make_float4(hi[4] + bb1.x + dB * c21.x, hi[5] + bb1.y + dB * c21.y,
                                 hi[6] + bb1.z + dB * c21.z, hi[7] + bb1.w + dB * c21.w);
        *(float4*)(Cb + (size_t)mA * Nr + n0 + tx * 8)           = rA0;
        *(float4*)(Cb + (size_t)mA * Nr + n0 + tx * 8 + 4)       = rA1;
        *(float4*)(Cb + (size_t)(mA + 1) * Nr + n0 + tx * 8)     = rB0;
        *(float4*)(Cb + (size_t)(mA + 1) * Nr + n0 + tx * 8 + 4) = rB1;
    }
}

// ---------------- warp-per-node CSR edge kernel, 4 channels per lane ----------------
// S[n][lane*4..+3] = sum_e silu(y[col_e] + lerp(tab, d_e)); shfl-broadcast metadata,
// no barriers, fully vectorized tab/y loads.
__global__ void __launch_bounds__(128)
edge_csr(const int* __restrict__ rp, const int* __restrict__ colp,
         const float* __restrict__ dvec, const float* __restrict__ y,
         const float2* __restrict__ tab, float* __restrict__ S) {
    int lane = threadIdx.x & 31;
    int n = blockIdx.x * 4 + (threadIdx.x >> 5);
    if (n >= Nn) return;
    int e0 = rp[n];
    int deg = rp[n + 1] - e0;
    const float* tf = (const float*)tab;
    float a0 = 0.f, a1 = 0.f, a2 = 0.f, a3 = 0.f;
    for (int base = 0; base < deg; base += 32) {
        int cnt = min(32, deg - base);
        float u_r = 0.f; int cc_r = 0;
        if (lane < cnt) {
            u_r = __ldg(dvec + e0 + base + lane) * SCALE;
            cc_r = __ldg(colp + e0 + base + lane);
        }
        for (int j = 0; j < cnt; j++) {
            float u = __shfl_sync(~0u, u_r, j);
            int cc = __shfl_sync(~0u, cc_r, j);
            int b = (int)u;
            float f = u - (float)b;
            const float4* trow = (const float4*)(tf + (b << 8)) + lane * 2;
            float4 t0 = __ldg(trow);
            float4 t1 = __ldg(trow + 1);
            float4 yv = __ldg((const float4*)(y + ((size_t)cc << 7)) + lane);
            float p0 = yv.x + fmaf(f, t0.y, t0.x);
            float p1 = yv.y + fmaf(f, t0.w, t0.z);
            float p2 = yv.z + fmaf(f, t1.y, t1.x);
            float p3 = yv.w + fmaf(f, t1.w, t1.z);
            a0 += silu_f(p0);
            a1 += silu_f(p1);
            a2 += silu_f(p2);
            a3 += silu_f(p3);
        }
    }
    *(float4*)(S + ((size_t)n << 7) + lane * 4) = make_float4(a0, a1, a2, a3);
}

// ---------------- fused GRU(l=3) + LayerNorm + pooling (+final via last block) ----------------
__global__ void __launch_bounds__(256)
ln_pool_all(const float* __restrict__ x, const float* __restrict__ gi,
            const float* __restrict__ bhh, const int* __restrict__ batch,
            const float* __restrict__ lg, const float* __restrict__ lb,
            float* __restrict__ out, float* __restrict__ sums,
            float* __restrict__ cnt, float* __restrict__ out2) {
    __shared__ int s_last;
    int warp = (blockIdx.x * blockDim.x + threadIdx.x) >> 5;
    int lane = threadIdx.x & 31;
    if (warp < Nn) {
        int ch = lane * 4;
        float4 v = __ldg((const float4*)(x + (size_t)warp * Hh + ch));
        const float* gm = gi + (size_t)warp * 384 + ch;
        float4 rv = __ldg((const float4*)(gm));
        float4 zv = __ldg((const float4*)(gm + 128));
        float4 nv = __ldg((const float4*)(gm + 256));
        float4 br = __ldg((const float4*)(bhh + ch));
        float4 bz = __ldg((const float4*)(bhh + 128 + ch));
        float4 bn = __ldg((const float4*)(bhh + 256 + ch));
        v.x = gru_upd(v.x, rv.x, zv.x, nv.x, br.x, bz.x, bn.x);
        v.y = gru_upd(v.y, rv.y, zv.y, nv.y, br.y, bz.y, bn.y);
        v.z = gru_upd(v.z, rv.z, zv.z, nv.z, br.z, bz.z, bn.z);
        v.w = gru_upd(v.w, rv.w, zv.w, nv.w, br.w, bz.w, bn.w);
        float s = v.x + v.y + v.z + v.w;
#pragma unroll
        for (int o = 16; o; o >>= 1) s += __shfl_xor_sync(~0u, s, o);
        float mu = s * (1.0f / 128.0f);
        float dx = v.x - mu, dy = v.y - mu, dz = v.z - mu, dw = v.w - mu;
        float vs = dx * dx + dy * dy + dz * dz + dw * dw;
#pragma unroll
        for (int o = 16; o; o >>= 1) vs += __shfl_xor_sync(~0u, vs, o);
        float inv = rsqrtf(vs * (1.0f / 128.0f) + 1e-5f);
        float o0 = dx * inv * lg[ch + 0] + lb[ch + 0];
        float o1 = dy * inv * lg[ch + 1] + lb[ch + 1];
        float o2 = dz * inv * lg[ch + 2] + lb[ch + 2];
        float o3 = dw * inv * lg[ch + 3] + lb[ch + 3];
        *(float4*)(out + (size_t)warp * Hh + ch) = make_float4(o0, o1, o2, o3);
        int bm = batch[warp];
        atomicAdd(&sums[bm * Hh + ch + 0], o0);
        atomicAdd(&sums[bm * Hh + ch + 1], o1);
        atomicAdd(&sums[bm * Hh + ch + 2], o2);
        atomicAdd(&sums[bm * Hh + ch + 3], o3);
        if (lane == 0) atomicAdd(&cnt[bm], 1.0f);
    }
    __syncthreads();
    if (threadIdx.x == 0) {
        __threadfence();
        int t = atomicAdd(&g_ctr, 1);
        s_last = (t == gridDim.x - 1) ? 1 : 0;
    }
    __syncthreads();
    if (s_last) {
        for (int i = threadIdx.x; i < Mm * Hh; i += blockDim.x) {
            float c = cnt[i >> 7];
            out2[i] = sums[i] / (c < 1.f ? 1.f : c);
        }
        if (threadIdx.x == 0) g_ctr = 0;
    }
}

// ---------------- host launcher ----------------
extern "C" void kernel_launch(void* const* d_in, const int* in_sizes, int n_in,
                              void* d_out, int out_size) {
    const int*   an    = (const int*)d_in[0];
    const float* pos   = (const float*)d_in[1];
    const int*   batch = (const int*)d_in[2];
    const int*   eidx  = (const int*)d_in[3];
    const float* emb   = (const float*)d_in[4];
    const float* W1    = (const float*)d_in[5];
    const float* b1    = (const float*)d_in[6];
    const float* W2    = (const float*)d_in[7];
    const float* b2    = (const float*)d_in[8];
    const float* W_ih  = (const float*)d_in[9];
    const float* b_ih  = (const float*)d_in[10];
    const float* b_hh  = (const float*)d_in[11];
    const float* ln_g  = (const float*)d_in[12];
    const float* ln_b  = (const float*)d_in[13];
    int E = in_sizes[3] / 2;
    if (E > EMAX) E = EMAX;
    const int* rowp = eidx;
    const int* colp = eidx + E;
    float* out = (float*)d_out;

    float *xp, *yp, *Sp, *gp, *dvp, *sp, *cp, *wcp, *bcp;
    float2* tp;
    int* rpp;
    cudaGetSymbolAddress((void**)&xp,  g_x);
    cudaGetSymbolAddress((void**)&yp,  g_y);
    cudaGetSymbolAddress((void**)&Sp,  g_S);
    cudaGetSymbolAddress((void**)&gp,  g_gi);
    cudaGetSymbolAddress((void**)&dvp, g_d);
    cudaGetSymbolAddress((void**)&rpp, g_rp);
    cudaGetSymbolAddress((void**)&sp,  g_sums);
    cudaGetSymbolAddress((void**)&cp,  g_cnt);
    cudaGetSymbolAddress((void**)&tp,  g_tab);
    cudaGetSymbolAddress((void**)&wcp, g_Wc);
    cudaGetSymbolAddress((void**)&bcp, g_bc2);

    // 1: init x/pads + zero sums/cnt + row_ptr
    int p0n = NP * Hh + Mm * Hh + Mm + E + 1;
    prep0<<<(p0n + 255) / 256, 256>>>(an, emb, rowp, E, xp, sp, cp, rpp);
    // 2: distances + rbf table + bc2
    int ndb = (E + 127) / 128;
    prep1<<<ndb + BINS * Ll + 12, 128>>>(pos, rowp, colp, E, ndb, W1, W_ih, b2,
                                         dvp, tp, bcp);
    const int Mt = NP / 128;
    for (int l = 0; l < Ll; l++) {
        const float* W1a = W1 + l * (Hh + Rr) * Hh;
        // y = x' @ W1a + b1   (x' = x + gru(gi_{l-1}) for l>0, stored back to x)
        gemm_f2b<<<dim3(1, Mt), 256>>>(xp, W1a, b1 + l * Hh, nullptr, nullptr,
                                       (l > 0) ? gp : nullptr,
                                       b_hh + (l - 1) * 3 * Hh, xp,
                                       yp, Hh, 0, 0, 0);
        // edge aggregation (warp-per-node CSR, no atomics, no barriers)
        edge_csr<<<(Nn + 3) / 4, 128>>>(rpp, colp, dvp, yp, tp + l * BINS * Hh, Sp);
        if (l == 0) {
            // Wc[l] = W2[l] @ W_ih[l], batched over layers
            gemm_f2b<<<dim3(3, 1, Ll), 256>>>(W2, W_ih, nullptr, nullptr, nullptr,
                                              nullptr, nullptr, nullptr,
                                              wcp, 3 * Hh,
                                              Hh * Hh, Hh * 3 * Hh, Hh * 3 * Hh);
        }
        // gi = S @ Wc + b_ih + deg (x) bc2
        gemm_f2b<<<dim3(3, Mt), 256>>>(Sp, wcp + l * Hh * 3 * Hh, b_ih + l * 3 * Hh,
                                       rpp, bcp + l * 3 * Hh,
                                       nullptr, nullptr, nullptr,
                                       gp, 3 * Hh, 0, 0, 0);
    }

    float* out_x = out;
    float* out_rep = out + Nn * Hh;
    if (out_size == Mm * Hh) { out_x = yp; out_rep = out; }
    // fused GRU(l=3) + LayerNorm + pool + finalize
    ln_pool_all<<<(Nn + 7) / 8, 256>>>(xp, gp, b_hh + 3 * 3 * Hh, batch,
                                       ln_g, ln_b, out_x, sp, cp, out_rep);
}